// round 5
// baseline (speedup 1.0000x reference)
#include <cuda_runtime.h>
#include <math.h>

// ---------------------------------------------------------------------------
// TCVAE loss — single launch, R3 structure (512-thr blocks, grid-stride,
// unroll-2) with an SM-balanced grid: 296 blocks = 2 CTAs on every SM.
//
// Algebra (ALPHA=BETA=GAMMA=1): pairwise logsumexp terms telescope away:
//   kl_loss = mean(log q(z|x)) - mean(log p(z))
// Remaining:
//   recon_loss = sum |x - recon| / (B*T)
//   kl_loss    = (1/B) * sum_{i,d} [ -0.5*((z-mu)^2*e^{-lv} + lv)
//                                    +0.5*( z^2*e^{-1}      + 1 ) ]
// ---------------------------------------------------------------------------

#define GRID_BLOCKS 296              // 2 CTAs per SM on 148 SMs, balanced
#define BLOCK_THREADS 512
#define NWARPS (BLOCK_THREADS / 32)

__device__ float2 g_partials[GRID_BLOCKS];
__device__ unsigned int g_ticket = 0;

__global__ void __launch_bounds__(BLOCK_THREADS) tcvae_fused_kernel(
    const float4* __restrict__ recon4,
    const float4* __restrict__ x4,
    int n_bt4,                       // (B*T)/4 = 262144
    const float4* __restrict__ mu4,
    const float4* __restrict__ lv4,
    const float4* __restrict__ z4,
    int n_bd4,                       // (B*D)/4 = 16384
    float* __restrict__ out,
    int n_bt, int batch)
{
    const float INV_E = 0.36787944117144233f;  // e^{-1}

    float racc = 0.0f;
    float kacc = 0.0f;

    int tid = blockIdx.x * BLOCK_THREADS + threadIdx.x;
    const int stride = GRID_BLOCKS * BLOCK_THREADS;   // 151552

    // KL term first (tiny; loads issue early and overlap the recon stream)
    for (int i = tid; i < n_bd4; i += stride) {
        float4 m = mu4[i];
        float4 l = lv4[i];
        float4 s = z4[i];
        float t;
        t = s.x - m.x; kacc += -0.5f * (t*t*__expf(-l.x) + l.x) + 0.5f * (s.x*s.x*INV_E + 1.0f);
        t = s.y - m.y; kacc += -0.5f * (t*t*__expf(-l.y) + l.y) + 0.5f * (s.y*s.y*INV_E + 1.0f);
        t = s.z - m.z; kacc += -0.5f * (t*t*__expf(-l.z) + l.z) + 0.5f * (s.z*s.z*INV_E + 1.0f);
        t = s.w - m.w; kacc += -0.5f * (t*t*__expf(-l.w) + l.w) + 0.5f * (s.w*s.w*INV_E + 1.0f);
    }

    // reconstruction L1 term, unroll-2 so 4 independent LDG.128 batch up front
    {
        int i = tid;
        for (; i + stride < n_bt4; i += 2 * stride) {
            float4 a0 = recon4[i];
            float4 a1 = recon4[i + stride];
            float4 b0 = x4[i];
            float4 b1 = x4[i + stride];
            racc += fabsf(b0.x - a0.x) + fabsf(b0.y - a0.y)
                  + fabsf(b0.z - a0.z) + fabsf(b0.w - a0.w);
            racc += fabsf(b1.x - a1.x) + fabsf(b1.y - a1.y)
                  + fabsf(b1.z - a1.z) + fabsf(b1.w - a1.w);
        }
        for (; i < n_bt4; i += stride) {
            float4 a = recon4[i];
            float4 b = x4[i];
            racc += fabsf(b.x - a.x) + fabsf(b.y - a.y)
                  + fabsf(b.z - a.z) + fabsf(b.w - a.w);
        }
    }

    // ---- block reduction ----
    #pragma unroll
    for (int o = 16; o > 0; o >>= 1) {
        racc += __shfl_xor_sync(0xFFFFFFFFu, racc, o);
        kacc += __shfl_xor_sync(0xFFFFFFFFu, kacc, o);
    }

    __shared__ float sr[NWARPS];
    __shared__ float sk[NWARPS];
    int lane = threadIdx.x & 31;
    int warp = threadIdx.x >> 5;
    if (lane == 0) { sr[warp] = racc; sk[warp] = kacc; }
    __syncthreads();

    __shared__ bool is_last;
    if (warp == 0) {
        racc = (lane < NWARPS) ? sr[lane] : 0.0f;
        kacc = (lane < NWARPS) ? sk[lane] : 0.0f;
        #pragma unroll
        for (int o = 8; o > 0; o >>= 1) {
            racc += __shfl_xor_sync(0xFFFFFFFFu, racc, o);
            kacc += __shfl_xor_sync(0xFFFFFFFFu, kacc, o);
        }
        if (lane == 0) {
            g_partials[blockIdx.x] = make_float2(racc, kacc);
            // acq_rel: release orders the partial store before the ticket
            // bump; acquire covers the last block's partial reads.
            unsigned int t;
            asm volatile("atom.acq_rel.gpu.global.add.u32 %0, [%1], 1;"
                         : "=r"(t) : "l"(&g_ticket) : "memory");
            is_last = (t == (unsigned int)(GRID_BLOCKS - 1));
        }
    }
    __syncthreads();

    // ---- last-block finalize (296 float2, strided warp gather) ----
    if (is_last) {
        float r = 0.0f, k = 0.0f;
        for (int i = threadIdx.x; i < GRID_BLOCKS; i += BLOCK_THREADS) {
            float2 p = g_partials[i];
            r += p.x;
            k += p.y;
        }
        #pragma unroll
        for (int o = 16; o > 0; o >>= 1) {
            r += __shfl_xor_sync(0xFFFFFFFFu, r, o);
            k += __shfl_xor_sync(0xFFFFFFFFu, k, o);
        }
        __shared__ double dr[NWARPS];
        __shared__ double dk[NWARPS];
        if (lane == 0) { dr[warp] = (double)r; dk[warp] = (double)k; }
        __syncthreads();
        if (threadIdx.x == 0) {
            double rs = 0.0, ks = 0.0;
            #pragma unroll
            for (int w = 0; w < NWARPS; w++) { rs += dr[w]; ks += dk[w]; }
            float recon_loss = (float)(rs / (double)n_bt);
            float kl_loss    = (float)(ks / (double)batch);
            out[0] = recon_loss + kl_loss;
            out[1] = recon_loss;
            out[2] = kl_loss;
            g_ticket = 0;  // reset for next graph replay (idempotent)
        }
    }
}

extern "C" void kernel_launch(void* const* d_in, const int* in_sizes, int n_in,
                              void* d_out, int out_size) {
    const float* recon   = (const float*)d_in[0];  // [B, T]
    const float* x       = (const float*)d_in[1];  // [B, T]
    const float* mu      = (const float*)d_in[2];  // [B, D]
    const float* log_var = (const float*)d_in[3];  // [B, D]
    const float* z       = (const float*)d_in[4];  // [B, D]
    // d_in[5] = dataset_size: unused (telescoping cancellation).

    int n_bt = in_sizes[0];          // B*T = 1048576
    int n_bd = in_sizes[2];          // B*D = 65536
    const int batch = 2048;          // B

    tcvae_fused_kernel<<<GRID_BLOCKS, BLOCK_THREADS>>>(
        (const float4*)recon, (const float4*)x, n_bt / 4,
        (const float4*)mu, (const float4*)log_var, (const float4*)z, n_bd / 4,
        (float*)d_out, n_bt, batch);
}

// round 6
// speedup vs baseline: 1.2286x; 1.2286x over previous
#include <cuda_runtime.h>
#include <math.h>

// ---------------------------------------------------------------------------
// TCVAE loss — single launch. Same work partition as the best-measured R3
// (131072 threads, stride 131072, unroll-2 recon => 4 front-batched LDG.128
// per thread), but 256-thread CTAs (4 CTAs/SM: more independent warp groups
// for the arbiter to interleave during load-wait, cheaper 8-warp barriers)
// and __ldcs streaming loads (use-once data, skip L1 allocation).
//
// Algebra (ALPHA=BETA=GAMMA=1): pairwise logsumexp terms telescope away:
//   kl_loss = mean(log q(z|x)) - mean(log p(z))
// Remaining:
//   recon_loss = sum |x - recon| / (B*T)
//   kl_loss    = (1/B) * sum_{i,d} [ -0.5*((z-mu)^2*e^{-lv} + lv)
//                                    +0.5*( z^2*e^{-1}      + 1 ) ]
// ---------------------------------------------------------------------------

#define GRID_BLOCKS 512
#define BLOCK_THREADS 256
#define NWARPS (BLOCK_THREADS / 32)   // 8

__device__ float2 g_partials[GRID_BLOCKS];
__device__ unsigned int g_ticket = 0;

__global__ void __launch_bounds__(BLOCK_THREADS) tcvae_fused_kernel(
    const float4* __restrict__ recon4,
    const float4* __restrict__ x4,
    int n_bt4,                       // (B*T)/4 = 262144
    const float4* __restrict__ mu4,
    const float4* __restrict__ lv4,
    const float4* __restrict__ z4,
    int n_bd4,                       // (B*D)/4 = 16384
    float* __restrict__ out,
    int n_bt, int batch)
{
    const float INV_E = 0.36787944117144233f;  // e^{-1}

    float racc = 0.0f;
    float kacc = 0.0f;

    int tid = blockIdx.x * BLOCK_THREADS + threadIdx.x;
    const int stride = GRID_BLOCKS * BLOCK_THREADS;   // 131072

    // KL term first (only tid < 16384; loads overlap the recon stream)
    for (int i = tid; i < n_bd4; i += stride) {
        float4 m = __ldcs(&mu4[i]);
        float4 l = __ldcs(&lv4[i]);
        float4 s = __ldcs(&z4[i]);
        float t;
        t = s.x - m.x; kacc += -0.5f * (t*t*__expf(-l.x) + l.x) + 0.5f * (s.x*s.x*INV_E + 1.0f);
        t = s.y - m.y; kacc += -0.5f * (t*t*__expf(-l.y) + l.y) + 0.5f * (s.y*s.y*INV_E + 1.0f);
        t = s.z - m.z; kacc += -0.5f * (t*t*__expf(-l.z) + l.z) + 0.5f * (s.z*s.z*INV_E + 1.0f);
        t = s.w - m.w; kacc += -0.5f * (t*t*__expf(-l.w) + l.w) + 0.5f * (s.w*s.w*INV_E + 1.0f);
    }

    // reconstruction L1 term, unroll-2: 4 independent LDG.128 batch up front
    {
        int i = tid;
        for (; i + stride < n_bt4; i += 2 * stride) {
            float4 a0 = __ldcs(&recon4[i]);
            float4 a1 = __ldcs(&recon4[i + stride]);
            float4 b0 = __ldcs(&x4[i]);
            float4 b1 = __ldcs(&x4[i + stride]);
            racc += fabsf(b0.x - a0.x) + fabsf(b0.y - a0.y)
                  + fabsf(b0.z - a0.z) + fabsf(b0.w - a0.w);
            racc += fabsf(b1.x - a1.x) + fabsf(b1.y - a1.y)
                  + fabsf(b1.z - a1.z) + fabsf(b1.w - a1.w);
        }
        for (; i < n_bt4; i += stride) {
            float4 a = __ldcs(&recon4[i]);
            float4 b = __ldcs(&x4[i]);
            racc += fabsf(b.x - a.x) + fabsf(b.y - a.y)
                  + fabsf(b.z - a.z) + fabsf(b.w - a.w);
        }
    }

    // ---- block reduction (8 warps) ----
    #pragma unroll
    for (int o = 16; o > 0; o >>= 1) {
        racc += __shfl_xor_sync(0xFFFFFFFFu, racc, o);
        kacc += __shfl_xor_sync(0xFFFFFFFFu, kacc, o);
    }

    __shared__ float sr[NWARPS];
    __shared__ float sk[NWARPS];
    int lane = threadIdx.x & 31;
    int warp = threadIdx.x >> 5;
    if (lane == 0) { sr[warp] = racc; sk[warp] = kacc; }
    __syncthreads();

    __shared__ bool is_last;
    if (warp == 0) {
        racc = (lane < NWARPS) ? sr[lane] : 0.0f;
        kacc = (lane < NWARPS) ? sk[lane] : 0.0f;
        #pragma unroll
        for (int o = 4; o > 0; o >>= 1) {
            racc += __shfl_xor_sync(0xFFFFFFFFu, racc, o);
            kacc += __shfl_xor_sync(0xFFFFFFFFu, kacc, o);
        }
        if (lane == 0) {
            g_partials[blockIdx.x] = make_float2(racc, kacc);
            // acq_rel: release orders the partial store before the ticket
            // bump; acquire covers the last block's partial reads.
            unsigned int t;
            asm volatile("atom.acq_rel.gpu.global.add.u32 %0, [%1], 1;"
                         : "=r"(t) : "l"(&g_ticket) : "memory");
            is_last = (t == (unsigned int)(GRID_BLOCKS - 1));
        }
    }
    __syncthreads();

    // ---- last-block finalize (512 float2 = 4KB, 2 gathers/thread) ----
    if (is_last) {
        float r = 0.0f, k = 0.0f;
        #pragma unroll
        for (int i = threadIdx.x; i < GRID_BLOCKS; i += BLOCK_THREADS) {
            float2 p = g_partials[i];
            r += p.x;
            k += p.y;
        }
        #pragma unroll
        for (int o = 16; o > 0; o >>= 1) {
            r += __shfl_xor_sync(0xFFFFFFFFu, r, o);
            k += __shfl_xor_sync(0xFFFFFFFFu, k, o);
        }
        __shared__ double dr[NWARPS];
        __shared__ double dk[NWARPS];
        if (lane == 0) { dr[warp] = (double)r; dk[warp] = (double)k; }
        __syncthreads();
        if (threadIdx.x == 0) {
            double rs = 0.0, ks = 0.0;
            #pragma unroll
            for (int w = 0; w < NWARPS; w++) { rs += dr[w]; ks += dk[w]; }
            float recon_loss = (float)(rs / (double)n_bt);
            float kl_loss    = (float)(ks / (double)batch);
            out[0] = recon_loss + kl_loss;
            out[1] = recon_loss;
            out[2] = kl_loss;
            g_ticket = 0;  // reset for next graph replay (idempotent)
        }
    }
}

extern "C" void kernel_launch(void* const* d_in, const int* in_sizes, int n_in,
                              void* d_out, int out_size) {
    const float* recon   = (const float*)d_in[0];  // [B, T]
    const float* x       = (const float*)d_in[1];  // [B, T]
    const float* mu      = (const float*)d_in[2];  // [B, D]
    const float* log_var = (const float*)d_in[3];  // [B, D]
    const float* z       = (const float*)d_in[4];  // [B, D]
    // d_in[5] = dataset_size: unused (telescoping cancellation).

    int n_bt = in_sizes[0];          // B*T = 1048576
    int n_bd = in_sizes[2];          // B*D = 65536
    const int batch = 2048;          // B

    tcvae_fused_kernel<<<GRID_BLOCKS, BLOCK_THREADS>>>(
        (const float4*)recon, (const float4*)x, n_bt / 4,
        (const float4*)mu, (const float4*)log_var, (const float4*)z, n_bd / 4,
        (float*)d_out, n_bt, batch);
}